// round 10
// baseline (speedup 1.0000x reference)
#include <cuda_runtime.h>

// CapsuleLayer dynamic routing. C=10,B=128,N=1152,IN=8,OUT=16, 3 iters.
// Three kernels:
//   1) transpose W -> Wt4[c][j][n], x -> xT4[b][j][n]   (n innermost)
//   2) priors GEMM -> g_pri[c][b][g][n]  (4 batches/thread, 64-reg acc,
//      barrier-free streaming; W operand read once per 4 batches)
//   3) routing: one CTA per (c, batch-pair), 576 threads; loads priors
//      coalesced (regs for node tid, thread-private smem for tid+576),
//      then 3 fused shift-free-softmax routing sweeps (exact).

#define CCAP   10
#define BD     128
#define ND     1152
#define OUTD   16
#define HALF   576

#define WT_ELEMS  (CCAP * 32 * ND)     // 368,640 float4 (5.9 MB)
#define XT_ELEMS  (BD * 2 * ND)        // 294,912 float4 (4.7 MB)
#define PRI_ELEMS (CCAP * BD * 4 * ND) // 5,898,240 float4 (94.4 MB)

__device__ float4 g_Wt[WT_ELEMS];
__device__ float4 g_xT[XT_ELEMS];
__device__ float4 g_pri[PRI_ELEMS];

// ---------------- Kernel 1: transposes ----------------
__global__ void transpose_inputs_kernel(const float4* __restrict__ W4,
                                        const float4* __restrict__ X4)
{
    int idx = blockIdx.x * blockDim.x + threadIdx.x;
    if (idx < WT_ELEMS) {
        int n = idx % ND;
        int t = idx / ND;
        int j = t % 32;
        int c = t / 32;
        g_Wt[idx] = W4[((size_t)c * ND + n) * 32 + j];
    } else if (idx < WT_ELEMS + XT_ELEMS) {
        int k = idx - WT_ELEMS;
        int n = k % ND;
        int t = k / ND;
        int j = t % 2;
        int b = t / 2;
        g_xT[k] = X4[((size_t)b * ND + n) * 2 + j];
    }
}

// ---------------- Kernel 2: priors GEMM ----------------
// CTA: 256 threads = 2 half-CTAs of 128 nodes x 4 batches.
// grid = 9 nchunks * 16 bgroups * 10 c = 1440.
#define PB_THREADS 256
#define PB_BLOCKS  (9 * 16 * CCAP)

__global__ __launch_bounds__(PB_THREADS)
void priors_kernel()
{
    const int tid = threadIdx.x;
    const int nl  = tid & 127;
    const int bh  = tid >> 7;            // 0/1
    const int bid = blockIdx.x;
    const int nchunk = bid % 9;
    const int t2  = bid / 9;
    const int bg  = t2 & 15;
    const int c   = t2 >> 4;
    const int n   = nchunk * 128 + nl;   // lane -> n consecutive
    const int b0  = bg * 8 + bh * 4;

    float xs[4][8];
    #pragma unroll
    for (int b = 0; b < 4; b++) {
        float4 u0 = g_xT[(size_t)((b0 + b) * 2) * ND + n];
        float4 u1 = g_xT[(size_t)((b0 + b) * 2 + 1) * ND + n];
        xs[b][0]=u0.x; xs[b][1]=u0.y; xs[b][2]=u0.z; xs[b][3]=u0.w;
        xs[b][4]=u1.x; xs[b][5]=u1.y; xs[b][6]=u1.z; xs[b][7]=u1.w;
    }

    float acc[4][16];
    #pragma unroll
    for (int b = 0; b < 4; b++)
        #pragma unroll
        for (int o = 0; o < 16; o++) acc[b][o] = 0.f;

    const float4* wp = g_Wt + (size_t)c * 32 * ND + n;
    #pragma unroll
    for (int j = 0; j < 32; j++) {
        float4 wv = wp[(size_t)j * ND];
        const int i = j >> 2, q = j & 3;
        #pragma unroll
        for (int b = 0; b < 4; b++) {
            const float xv = xs[b][i];
            acc[b][4*q+0] += xv * wv.x;
            acc[b][4*q+1] += xv * wv.y;
            acc[b][4*q+2] += xv * wv.z;
            acc[b][4*q+3] += xv * wv.w;
        }
    }

    #pragma unroll
    for (int b = 0; b < 4; b++)
        #pragma unroll
        for (int g = 0; g < 4; g++)
            g_pri[(size_t)(((c * BD + b0 + b) * 4) + g) * ND + n] =
                make_float4(acc[b][4*g], acc[b][4*g+1], acc[b][4*g+2], acc[b][4*g+3]);
}

// ---------------- Kernel 3: routing ----------------
#define RT_THREADS 576
#define NWARPS     18
#define RT_BLOCKS  (CCAP * BD / 2)   // 640

// shared memory layout (floats)
#define PRI_SZ    (2 * 16 * HALF)          // 18432 : pri4[bb][g][n] float4-packed
#define VRED_OFF  PRI_SZ
#define VRED_SZ   (NWARPS * 32)
#define SPRED_OFF (VRED_OFF + VRED_SZ)
#define OUTV_OFF  (SPRED_OFF + 2 * NWARPS)
#define SMEM_FLOATS (OUTV_OFF + 32)
#define SMEM_BYTES  (SMEM_FLOATS * 4)      // ~76.3 KB

__global__ __launch_bounds__(RT_THREADS, 1)
void routing_kernel(float* __restrict__ out)
{
    extern __shared__ float sm[];
    float4* pri4  = (float4*)sm;        // [2][4][HALF] float4 (thread-private)
    float*  vred  = sm + VRED_OFF;      // [18][32]
    float*  spred = sm + SPRED_OFF;     // [18][2]
    float*  outv  = sm + OUTV_OFF;      // [2][16]

    const int tid  = threadIdx.x;
    const int lane = tid & 31;
    const int w    = tid >> 5;           // 0..17
    const int c    = blockIdx.x >> 6;
    const int b0   = (blockIdx.x & 63) * 2;

    // ---- load priors: node tid -> registers, node tid+576 -> smem ----
    float priA0[16], priA1[16];
    const float4* pr0 = g_pri + (size_t)((c * BD + b0) * 4) * ND;
    const float4* pr1 = g_pri + (size_t)((c * BD + b0 + 1) * 4) * ND;

    #pragma unroll
    for (int g = 0; g < 4; g++) {
        float4 q0 = pr0[(size_t)g * ND + tid];
        float4 q1 = pr1[(size_t)g * ND + tid];
        priA0[4*g+0]=q0.x; priA0[4*g+1]=q0.y; priA0[4*g+2]=q0.z; priA0[4*g+3]=q0.w;
        priA1[4*g+0]=q1.x; priA1[4*g+1]=q1.y; priA1[4*g+2]=q1.z; priA1[4*g+3]=q1.w;
    }
    #pragma unroll
    for (int g = 0; g < 4; g++) {
        pri4[g * HALF + tid]       = pr0[(size_t)g * ND + tid + HALF];
        pri4[(4 + g) * HALF + tid] = pr1[(size_t)g * ND + tid + HALF];
    }
    // no barrier: each thread reads only the smem words it wrote.

    const float4* __restrict__ P0 = pri4 + tid;            // + g*HALF (bb=0)
    const float4* __restrict__ P1 = pri4 + 4 * HALF + tid; // + g*HALF (bb=1)

    // logits (shift-free): a = node tid, b = node tid+576; 0/1 = batch
    float la0 = 0.f, la1 = 0.f, lb0 = 0.f, lb1 = 0.f;

    // ---------------- 3 fused routing sweeps ----------------
    #pragma unroll 1
    for (int it = 0; it < 3; it++) {
        float v0[16], v1[16];
        float sp0 = 0.f, sp1 = 0.f;

        if (it == 0) {
            // logits == 0: attention exactly uniform; S = ND.
            #pragma unroll
            for (int g = 0; g < 4; g++) {
                float4 q0 = P0[g * HALF];
                float4 q1 = P1[g * HALF];
                v0[4*g+0] = priA0[4*g+0] + q0.x; v0[4*g+1] = priA0[4*g+1] + q0.y;
                v0[4*g+2] = priA0[4*g+2] + q0.z; v0[4*g+3] = priA0[4*g+3] + q0.w;
                v1[4*g+0] = priA1[4*g+0] + q1.x; v1[4*g+1] = priA1[4*g+1] + q1.y;
                v1[4*g+2] = priA1[4*g+2] + q1.z; v1[4*g+3] = priA1[4*g+3] + q1.w;
            }
        } else {
            // fused: logit update -> exp -> weighted accumulation, one sweep.
            // batch 0
            {
                float d = 0.f;
                #pragma unroll
                for (int o = 0; o < 16; o++) d += outv[o] * priA0[o];
                la0 += d;
                float e = __expf(la0);
                sp0 = e;
                #pragma unroll
                for (int o = 0; o < 16; o++) v0[o] = e * priA0[o];

                float p[16];
                d = 0.f;
                #pragma unroll
                for (int g = 0; g < 4; g++) {
                    float4 q = P0[g * HALF];
                    p[4*g+0] = q.x; p[4*g+1] = q.y; p[4*g+2] = q.z; p[4*g+3] = q.w;
                    d += outv[4*g+0] * q.x + outv[4*g+1] * q.y
                       + outv[4*g+2] * q.z + outv[4*g+3] * q.w;
                }
                lb0 += d;
                e = __expf(lb0);
                sp0 += e;
                #pragma unroll
                for (int o = 0; o < 16; o++) v0[o] += e * p[o];
            }
            // batch 1
            {
                float d = 0.f;
                #pragma unroll
                for (int o = 0; o < 16; o++) d += outv[16 + o] * priA1[o];
                la1 += d;
                float e = __expf(la1);
                sp1 = e;
                #pragma unroll
                for (int o = 0; o < 16; o++) v1[o] = e * priA1[o];

                float p[16];
                d = 0.f;
                #pragma unroll
                for (int g = 0; g < 4; g++) {
                    float4 q = P1[g * HALF];
                    p[4*g+0] = q.x; p[4*g+1] = q.y; p[4*g+2] = q.z; p[4*g+3] = q.w;
                    d += outv[16+4*g+0] * q.x + outv[16+4*g+1] * q.y
                       + outv[16+4*g+2] * q.z + outv[16+4*g+3] * q.w;
                }
                lb1 += d;
                e = __expf(lb1);
                sp1 += e;
                #pragma unroll
                for (int o = 0; o < 16; o++) v1[o] += e * p[o];
            }
        }

        // batch-merging component-splitting warp reduce (31 shfl):
        // bit-16 merges batches; bits 8/4/2/1 split components.
        float v[16];
        #pragma unroll
        for (int k = 0; k < 16; k++) {
            float s = (lane & 16) ? v0[k] : v1[k];
            float r = __shfl_xor_sync(0xffffffffu, s, 16);
            v[k] = ((lane & 16) ? v1[k] : v0[k]) + r;
        }
        #pragma unroll
        for (int k = 0; k < 8; k++) {
            float s = (lane & 8) ? v[k] : v[k + 8];
            float r = __shfl_xor_sync(0xffffffffu, s, 8);
            v[k] = ((lane & 8) ? v[k + 8] : v[k]) + r;
        }
        #pragma unroll
        for (int k = 0; k < 4; k++) {
            float s = (lane & 4) ? v[k] : v[k + 4];
            float r = __shfl_xor_sync(0xffffffffu, s, 4);
            v[k] = ((lane & 4) ? v[k + 4] : v[k]) + r;
        }
        #pragma unroll
        for (int k = 0; k < 2; k++) {
            float s = (lane & 2) ? v[k] : v[k + 2];
            float r = __shfl_xor_sync(0xffffffffu, s, 2);
            v[k] = ((lane & 2) ? v[k + 2] : v[k]) + r;
        }
        {
            float s = (lane & 1) ? v[0] : v[1];
            float r = __shfl_xor_sync(0xffffffffu, s, 1);
            v[0] = ((lane & 1) ? v[1] : v[0]) + r;
        }
        vred[w * 32 + lane] = v[0];

        if (it > 0) {   // sp: merge batches then butterfly
            float s = (lane & 16) ? sp0 : sp1;
            float r = __shfl_xor_sync(0xffffffffu, s, 16);
            float sp = ((lane & 16) ? sp1 : sp0) + r;
            #pragma unroll
            for (int d = 8; d; d >>= 1)
                sp += __shfl_xor_sync(0xffffffffu, sp, d);
            if ((lane & 15) == 0) spred[w * 2 + (lane >> 4)] = sp;
        }
        __syncthreads();

        // --- final 18-way reduce + squash (warp 0: lanes 0-15 bb0, 16-31 bb1) ---
        if (tid < 32) {
            const int fb = tid >> 4;
            float O = 0.f;
            #pragma unroll
            for (int j = 0; j < NWARPS; j++) O += vred[j * 32 + tid];
            float S;
            if (it == 0) {
                S = (float)ND;
            } else {
                S = 0.f;
                #pragma unroll
                for (int j = 0; j < NWARPS; j++) S += spred[j * 2 + fb];
            }
            float t = O / S;
            float sq = t * t;
            #pragma unroll
            for (int d = 8; d; d >>= 1)
                sq += __shfl_xor_sync(0xffffffffu, sq, d);
            float scale = sq / ((1.f + sq) * sqrtf(sq + 1e-8f));
            float val = t * scale;
            outv[tid] = val;
            if (it == 2)
                out[((size_t)(c * BD + b0 + fb)) * OUTD + (tid & 15)] = val;
        }
        __syncthreads();
    }
}

extern "C" void kernel_launch(void* const* d_in, const int* in_sizes, int n_in,
                              void* d_out, int out_size)
{
    const float* x = (const float*)d_in[0];
    const float* W = (const float*)d_in[1];
    // defensive: identify by size (x: 1,179,648 ; W: 1,474,560)
    if (n_in >= 2 && in_sizes[0] == CCAP * ND * 8 * OUTD) {
        x = (const float*)d_in[1];
        W = (const float*)d_in[0];
    }
    float* out = (float*)d_out;

    const int ttotal = WT_ELEMS + XT_ELEMS;
    transpose_inputs_kernel<<<(ttotal + 255) / 256, 256>>>(
        (const float4*)W, (const float4*)x);

    priors_kernel<<<PB_BLOCKS, PB_THREADS>>>();

    cudaFuncSetAttribute(routing_kernel,
                         cudaFuncAttributeMaxDynamicSharedMemorySize, SMEM_BYTES);
    routing_kernel<<<RT_BLOCKS, RT_THREADS, SMEM_BYTES>>>(out);
}

// round 11
// speedup vs baseline: 1.2879x; 1.2879x over previous
#include <cuda_runtime.h>

// CapsuleLayer dynamic routing. C=10,B=128,N=1152,IN=8,OUT=16, 3 iters.
//   1) tiled transpose W -> Wt4[c][j][n]; simple transpose x -> xT4[b][j][n]
//   2) fused priors + routing, one CTA per (c, batch-pair), 576 threads.
// Iteration-0 (logits==0 -> uniform attention) is folded into the priors
// GEMM: the uniform sums accumulate in registers, so phase B runs only two
// smem sweeps (fused shift-free-softmax logit-update/accumulation, exact).
// pri_s is thread-private (each thread reads only what it wrote): no
// barrier between the GEMM and the routing sweeps except around vred.

#define CCAP   10
#define BD     128
#define ND     1152
#define OUTD   16
#define HALF   576
#define THREADS 576
#define NWARPS  18
#define NBLOCKS (CCAP * BD / 2)   // 640

#define WT_ELEMS (CCAP * 32 * ND)   // 368,640 float4 (5.9 MB)
#define XT_ELEMS (BD * 2 * ND)      // 294,912 float4 (4.7 MB)

__device__ float4 g_Wt[WT_ELEMS];
__device__ float4 g_xT[XT_ELEMS];

// ---------------- Kernel 1: transposes ----------------
// blocks [0, 360): W, smem-tiled (both gmem sides coalesced)
// blocks [360, 648): x, output-coalesced gather (stride is only 32B)
#define TP_WBLOCKS (CCAP * 36)          // 360
#define TP_XBLOCKS (XT_ELEMS / 1024)    // 288

__global__ void transpose_inputs_kernel(const float4* __restrict__ W4,
                                        const float4* __restrict__ X4)
{
    if (blockIdx.x < TP_WBLOCKS) {
        __shared__ float4 tile[32][33];
        const int c  = blockIdx.x / 36;
        const int n0 = (blockIdx.x % 36) * 32;
        #pragma unroll
        for (int k = 0; k < 4; k++) {
            int flat = threadIdx.x + k * 256;
            int jr = flat & 31, nr = flat >> 5;
            tile[jr][nr] = W4[((size_t)(c * ND + n0 + nr)) * 32 + jr];
        }
        __syncthreads();
        #pragma unroll
        for (int k = 0; k < 4; k++) {
            int flat = threadIdx.x + k * 256;
            int nr = flat & 31, jr = flat >> 5;
            g_Wt[(size_t)(c * 32 + jr) * ND + n0 + nr] = tile[jr][nr];
        }
    } else {
        int base = (blockIdx.x - TP_WBLOCKS) * 1024 + threadIdx.x;
        #pragma unroll
        for (int k = 0; k < 4; k++) {
            int e = base + k * 256;
            int n = e % ND;
            int t = e / ND;
            int j = t & 1;
            int b = t >> 1;
            g_xT[e] = X4[((size_t)b * ND + n) * 2 + j];
        }
    }
}

// ---------------- Kernel 2: fused priors + routing ----------------
// shared memory layout (floats)
#define PRI_SZ    (2 * 16 * HALF)          // 18432 : pri4[bb][g][n] float4-packed
#define VRED_OFF  PRI_SZ
#define VRED_SZ   (NWARPS * 32)
#define SPRED_OFF (VRED_OFF + VRED_SZ)
#define OUTV_OFF  (SPRED_OFF + 2 * NWARPS)
#define SMEM_FLOATS (OUTV_OFF + 32)
#define SMEM_BYTES  (SMEM_FLOATS * 4)      // ~76.3 KB

__global__ __launch_bounds__(THREADS, 1)
void caps_routing_kernel(float* __restrict__ out)
{
    extern __shared__ float sm[];
    float4* pri4  = (float4*)sm;        // [2][4][HALF] float4 (thread-private)
    float*  vred  = sm + VRED_OFF;      // [18][32]
    float*  spred = sm + SPRED_OFF;     // [18][2]
    float*  outv  = sm + OUTV_OFF;      // [2][16]

    const int tid  = threadIdx.x;
    const int lane = tid & 31;
    const int w    = tid >> 5;           // 0..17
    const int c    = blockIdx.x >> 6;
    const int b0   = (blockIdx.x & 63) * 2;

    const float4* __restrict__ xr0 = g_xT + (size_t)(b0 * 2) * ND;
    const float4* __restrict__ xr1 = g_xT + (size_t)((b0 + 1) * 2) * ND;
    const float4* __restrict__ wbase = g_Wt + (size_t)c * 32 * ND;

    // -------- Phase A: priors GEMM + iteration-0 uniform sums --------
    float un0[16], un1[16];     // Sum over both reps (it-0 accumulation)
    float priA0[16], priA1[16]; // rep-0 priors (register-resident node)

    // rep 1 (smem node) first
    {
        const int n = tid + HALF;
        float4 u0 = xr0[n], u1 = xr0[ND + n];
        float4 u2 = xr1[n], u3 = xr1[ND + n];
        float xa[8] = {u0.x, u0.y, u0.z, u0.w, u1.x, u1.y, u1.z, u1.w};
        float xb[8] = {u2.x, u2.y, u2.z, u2.w, u3.x, u3.y, u3.z, u3.w};

        float acc0[16], acc1[16];
        #pragma unroll
        for (int o = 0; o < 16; o++) { acc0[o] = 0.f; acc1[o] = 0.f; }

        const float4* wp = wbase + n;
        #pragma unroll
        for (int i = 0; i < 8; i++) {
            const float va = xa[i], vb = xb[i];
            #pragma unroll
            for (int q = 0; q < 4; q++) {
                float4 wv = wp[(size_t)(i * 4 + q) * ND];
                acc0[4*q+0] += va * wv.x; acc0[4*q+1] += va * wv.y;
                acc0[4*q+2] += va * wv.z; acc0[4*q+3] += va * wv.w;
                acc1[4*q+0] += vb * wv.x; acc1[4*q+1] += vb * wv.y;
                acc1[4*q+2] += vb * wv.z; acc1[4*q+3] += vb * wv.w;
            }
        }
        #pragma unroll
        for (int g = 0; g < 4; g++) {
            pri4[g * HALF + tid] =
                make_float4(acc0[4*g], acc0[4*g+1], acc0[4*g+2], acc0[4*g+3]);
            pri4[(4 + g) * HALF + tid] =
                make_float4(acc1[4*g], acc1[4*g+1], acc1[4*g+2], acc1[4*g+3]);
        }
        #pragma unroll
        for (int o = 0; o < 16; o++) { un0[o] = acc0[o]; un1[o] = acc1[o]; }
    }
    // rep 0 (register node)
    {
        const int n = tid;
        float4 u0 = xr0[n], u1 = xr0[ND + n];
        float4 u2 = xr1[n], u3 = xr1[ND + n];
        float xa[8] = {u0.x, u0.y, u0.z, u0.w, u1.x, u1.y, u1.z, u1.w};
        float xb[8] = {u2.x, u2.y, u2.z, u2.w, u3.x, u3.y, u3.z, u3.w};

        #pragma unroll
        for (int o = 0; o < 16; o++) { priA0[o] = 0.f; priA1[o] = 0.f; }

        const float4* wp = wbase + n;
        #pragma unroll
        for (int i = 0; i < 8; i++) {
            const float va = xa[i], vb = xb[i];
            #pragma unroll
            for (int q = 0; q < 4; q++) {
                float4 wv = wp[(size_t)(i * 4 + q) * ND];
                priA0[4*q+0] += va * wv.x; priA0[4*q+1] += va * wv.y;
                priA0[4*q+2] += va * wv.z; priA0[4*q+3] += va * wv.w;
                priA1[4*q+0] += vb * wv.x; priA1[4*q+1] += vb * wv.y;
                priA1[4*q+2] += vb * wv.z; priA1[4*q+3] += vb * wv.w;
            }
        }
        // un = priA + un (commutative, bit-exact vs R9's it-0 order)
        #pragma unroll
        for (int o = 0; o < 16; o++) { un0[o] += priA0[o]; un1[o] += priA1[o]; }
    }
    // NOTE: no __syncthreads() — pri_s is thread-private.

    const float4* __restrict__ P0 = pri4 + tid;            // + g*HALF (bb=0)
    const float4* __restrict__ P1 = pri4 + 4 * HALF + tid; // + g*HALF (bb=1)

    float la0 = 0.f, la1 = 0.f, lb0 = 0.f, lb1 = 0.f;      // logits

    // ---------------- Phase B: iterations 0..2 ----------------
    #pragma unroll 1
    for (int it = 0; it < 3; it++) {
        float v0[16], v1[16];
        float sp0 = 0.f, sp1 = 0.f;

        if (it == 0) {
            #pragma unroll
            for (int o = 0; o < 16; o++) { v0[o] = un0[o]; v1[o] = un1[o]; }
        } else {
            // fused: logit update -> exp -> weighted accumulation, one sweep.
            // batch 0
            {
                float d = 0.f;
                #pragma unroll
                for (int o = 0; o < 16; o++) d += outv[o] * priA0[o];
                la0 += d;
                float e = __expf(la0);
                sp0 = e;
                #pragma unroll
                for (int o = 0; o < 16; o++) v0[o] = e * priA0[o];

                float p[16];
                d = 0.f;
                #pragma unroll
                for (int g = 0; g < 4; g++) {
                    float4 q = P0[g * HALF];
                    p[4*g+0] = q.x; p[4*g+1] = q.y; p[4*g+2] = q.z; p[4*g+3] = q.w;
                    d += outv[4*g+0] * q.x + outv[4*g+1] * q.y
                       + outv[4*g+2] * q.z + outv[4*g+3] * q.w;
                }
                lb0 += d;
                e = __expf(lb0);
                sp0 += e;
                #pragma unroll
                for (int o = 0; o < 16; o++) v0[o] += e * p[o];
            }
            // batch 1
            {
                float d = 0.f;
                #pragma unroll
                for (int o = 0; o < 16; o++) d += outv[16 + o] * priA1[o];
                la1 += d;
                float e = __expf(la1);
                sp1 = e;
                #pragma unroll
                for (int o = 0; o < 16; o++) v1[o] = e * priA1[o];

                float p[16];
                d = 0.f;
                #pragma unroll
                for (int g = 0; g < 4; g++) {
                    float4 q = P1[g * HALF];
                    p[4*g+0] = q.x; p[4*g+1] = q.y; p[4*g+2] = q.z; p[4*g+3] = q.w;
                    d += outv[16+4*g+0] * q.x + outv[16+4*g+1] * q.y
                       + outv[16+4*g+2] * q.z + outv[16+4*g+3] * q.w;
                }
                lb1 += d;
                e = __expf(lb1);
                sp1 += e;
                #pragma unroll
                for (int o = 0; o < 16; o++) v1[o] += e * p[o];
            }
        }

        // batch-merging component-splitting warp reduce (31 shfl):
        // bit-16 merges batches; bits 8/4/2/1 split components.
        float v[16];
        #pragma unroll
        for (int k = 0; k < 16; k++) {
            float s = (lane & 16) ? v0[k] : v1[k];
            float r = __shfl_xor_sync(0xffffffffu, s, 16);
            v[k] = ((lane & 16) ? v1[k] : v0[k]) + r;
        }
        #pragma unroll
        for (int k = 0; k < 8; k++) {
            float s = (lane & 8) ? v[k] : v[k + 8];
            float r = __shfl_xor_sync(0xffffffffu, s, 8);
            v[k] = ((lane & 8) ? v[k + 8] : v[k]) + r;
        }
        #pragma unroll
        for (int k = 0; k < 4; k++) {
            float s = (lane & 4) ? v[k] : v[k + 4];
            float r = __shfl_xor_sync(0xffffffffu, s, 4);
            v[k] = ((lane & 4) ? v[k + 4] : v[k]) + r;
        }
        #pragma unroll
        for (int k = 0; k < 2; k++) {
            float s = (lane & 2) ? v[k] : v[k + 2];
            float r = __shfl_xor_sync(0xffffffffu, s, 2);
            v[k] = ((lane & 2) ? v[k + 2] : v[k]) + r;
        }
        {
            float s = (lane & 1) ? v[0] : v[1];
            float r = __shfl_xor_sync(0xffffffffu, s, 1);
            v[0] = ((lane & 1) ? v[1] : v[0]) + r;
        }
        vred[w * 32 + lane] = v[0];

        if (it > 0) {   // sp: merge batches then butterfly
            float s = (lane & 16) ? sp0 : sp1;
            float r = __shfl_xor_sync(0xffffffffu, s, 16);
            float sp = ((lane & 16) ? sp1 : sp0) + r;
            #pragma unroll
            for (int d = 8; d; d >>= 1)
                sp += __shfl_xor_sync(0xffffffffu, sp, d);
            if ((lane & 15) == 0) spred[w * 2 + (lane >> 4)] = sp;
        }
        __syncthreads();

        // --- final 18-way reduce + squash (warp 0: lanes 0-15 bb0, 16-31 bb1) ---
        if (tid < 32) {
            const int fb = tid >> 4;
            float O = 0.f;
            #pragma unroll
            for (int j = 0; j < NWARPS; j++) O += vred[j * 32 + tid];
            float S;
            if (it == 0) {
                S = (float)ND;
            } else {
                S = 0.f;
                #pragma unroll
                for (int j = 0; j < NWARPS; j++) S += spred[j * 2 + fb];
            }
            float t = O / S;
            float sq = t * t;
            #pragma unroll
            for (int d = 8; d; d >>= 1)
                sq += __shfl_xor_sync(0xffffffffu, sq, d);
            float scale = sq / ((1.f + sq) * sqrtf(sq + 1e-8f));
            float val = t * scale;
            outv[tid] = val;
            if (it == 2)
                out[((size_t)(c * BD + b0 + fb)) * OUTD + (tid & 15)] = val;
        }
        __syncthreads();
    }
}

extern "C" void kernel_launch(void* const* d_in, const int* in_sizes, int n_in,
                              void* d_out, int out_size)
{
    const float* x = (const float*)d_in[0];
    const float* W = (const float*)d_in[1];
    // defensive: identify by size (x: 1,179,648 ; W: 1,474,560)
    if (n_in >= 2 && in_sizes[0] == CCAP * ND * 8 * OUTD) {
        x = (const float*)d_in[1];
        W = (const float*)d_in[0];
    }
    float* out = (float*)d_out;

    transpose_inputs_kernel<<<TP_WBLOCKS + TP_XBLOCKS, 256>>>(
        (const float4*)W, (const float4*)x);

    cudaFuncSetAttribute(caps_routing_kernel,
                         cudaFuncAttributeMaxDynamicSharedMemorySize, SMEM_BYTES);
    caps_routing_kernel<<<NBLOCKS, THREADS, SMEM_BYTES>>>(out);
}

// round 12
// speedup vs baseline: 1.3050x; 1.0132x over previous
#include <cuda_runtime.h>

// CapsuleLayer dynamic routing. C=10,B=128,N=1152,IN=8,OUT=16, 3 iters.
//   1) tiled transpose W -> Wt4[c][j][n]; simple transpose x -> xT4[b][j][n]
//   2) fused priors + routing, one CTA per (c, batch-pair), 576 threads.
// ALL priors register-resident: thread owns nodes tid and tid+576 for both
// batches (4x16 = 64 regs). No priors smem plane, no STS/LDS sweeps --
// phase B is pure FFMA + warp shuffles. Shift-free softmax (exact; shift
// cancels), fused logit-update/accumulation; iteration 0 uses logits==0 ->
// uniform attention (S = N), computed directly as priA + priB.

#define CCAP   10
#define BD     128
#define ND     1152
#define OUTD   16
#define HALF   576
#define THREADS 576
#define NWARPS  18
#define NBLOCKS (CCAP * BD / 2)   // 640

#define WT_ELEMS (CCAP * 32 * ND)   // 368,640 float4 (5.9 MB)
#define XT_ELEMS (BD * 2 * ND)      // 294,912 float4 (4.7 MB)

__device__ float4 g_Wt[WT_ELEMS];
__device__ float4 g_xT[XT_ELEMS];

// ---------------- Kernel 1: transposes ----------------
#define TP_WBLOCKS (CCAP * 36)          // 360
#define TP_XBLOCKS (XT_ELEMS / 1024)    // 288

__global__ void transpose_inputs_kernel(const float4* __restrict__ W4,
                                        const float4* __restrict__ X4)
{
    if (blockIdx.x < TP_WBLOCKS) {
        __shared__ float4 tile[32][33];
        const int c  = blockIdx.x / 36;
        const int n0 = (blockIdx.x % 36) * 32;
        #pragma unroll
        for (int k = 0; k < 4; k++) {
            int flat = threadIdx.x + k * 256;
            int jr = flat & 31, nr = flat >> 5;
            tile[jr][nr] = W4[((size_t)(c * ND + n0 + nr)) * 32 + jr];
        }
        __syncthreads();
        #pragma unroll
        for (int k = 0; k < 4; k++) {
            int flat = threadIdx.x + k * 256;
            int nr = flat & 31, jr = flat >> 5;
            g_Wt[(size_t)(c * 32 + jr) * ND + n0 + nr] = tile[jr][nr];
        }
    } else {
        int base = (blockIdx.x - TP_WBLOCKS) * 1024 + threadIdx.x;
        #pragma unroll
        for (int k = 0; k < 4; k++) {
            int e = base + k * 256;
            int n = e % ND;
            int t = e / ND;
            int j = t & 1;
            int b = t >> 1;
            g_xT[e] = X4[((size_t)b * ND + n) * 2 + j];
        }
    }
}

// ---------------- Kernel 2: fused priors + routing ----------------
__global__ __launch_bounds__(THREADS, 1)
void caps_routing_kernel(float* __restrict__ out)
{
    __shared__ float vred[NWARPS * 32];
    __shared__ float spred[NWARPS * 2];
    __shared__ float outv[32];

    const int tid  = threadIdx.x;
    const int lane = tid & 31;
    const int w    = tid >> 5;           // 0..17
    const int c    = blockIdx.x >> 6;
    const int b0   = (blockIdx.x & 63) * 2;

    const float4* __restrict__ xr0 = g_xT + (size_t)(b0 * 2) * ND;
    const float4* __restrict__ xr1 = g_xT + (size_t)((b0 + 1) * 2) * ND;
    const float4* __restrict__ wbase = g_Wt + (size_t)c * 32 * ND;

    // -------- Phase A: priors, both nodes fully register-resident --------
    float priA0[16], priA1[16];   // node tid      (batch 0 / 1)
    float priB0[16], priB1[16];   // node tid+576  (batch 0 / 1)

    #pragma unroll
    for (int rep = 0; rep < 2; rep++) {
        const int n = tid + rep * HALF;
        float4 u0 = xr0[n], u1 = xr0[ND + n];
        float4 u2 = xr1[n], u3 = xr1[ND + n];
        float xa[8] = {u0.x, u0.y, u0.z, u0.w, u1.x, u1.y, u1.z, u1.w};
        float xb[8] = {u2.x, u2.y, u2.z, u2.w, u3.x, u3.y, u3.z, u3.w};

        float* a0 = rep ? priB0 : priA0;
        float* a1 = rep ? priB1 : priA1;
        #pragma unroll
        for (int o = 0; o < 16; o++) { a0[o] = 0.f; a1[o] = 0.f; }

        const float4* wp = wbase + n;
        #pragma unroll
        for (int i = 0; i < 8; i++) {
            const float va = xa[i], vb = xb[i];
            #pragma unroll
            for (int q = 0; q < 4; q++) {
                float4 wv = wp[(size_t)(i * 4 + q) * ND];
                a0[4*q+0] += va * wv.x; a0[4*q+1] += va * wv.y;
                a0[4*q+2] += va * wv.z; a0[4*q+3] += va * wv.w;
                a1[4*q+0] += vb * wv.x; a1[4*q+1] += vb * wv.y;
                a1[4*q+2] += vb * wv.z; a1[4*q+3] += vb * wv.w;
            }
        }
    }

    float la0 = 0.f, la1 = 0.f, lb0 = 0.f, lb1 = 0.f;      // logits

    // ---------------- Phase B: iterations 0..2 (register-only) ----------------
    #pragma unroll 1
    for (int it = 0; it < 3; it++) {
        float v0[16], v1[16];
        float sp0 = 0.f, sp1 = 0.f;

        if (it == 0) {
            // logits == 0: attention exactly uniform; S = ND.
            #pragma unroll
            for (int o = 0; o < 16; o++) {
                v0[o] = priB0[o] + priA0[o];
                v1[o] = priB1[o] + priA1[o];
            }
        } else {
            // fused: logit update -> exp -> weighted accumulation.
            // batch 0
            {
                float dA = 0.f, dB = 0.f;
                #pragma unroll
                for (int o = 0; o < 16; o++) {
                    const float ov = outv[o];
                    dA += ov * priA0[o];
                    dB += ov * priB0[o];
                }
                la0 += dA; lb0 += dB;
                float eA = __expf(la0);
                float eB = __expf(lb0);
                sp0 = eA + eB;
                #pragma unroll
                for (int o = 0; o < 16; o++)
                    v0[o] = eA * priA0[o] + eB * priB0[o];
            }
            // batch 1
            {
                float dA = 0.f, dB = 0.f;
                #pragma unroll
                for (int o = 0; o < 16; o++) {
                    const float ov = outv[16 + o];
                    dA += ov * priA1[o];
                    dB += ov * priB1[o];
                }
                la1 += dA; lb1 += dB;
                float eA = __expf(la1);
                float eB = __expf(lb1);
                sp1 = eA + eB;
                #pragma unroll
                for (int o = 0; o < 16; o++)
                    v1[o] = eA * priA1[o] + eB * priB1[o];
            }
        }

        // batch-merging component-splitting warp reduce (31 shfl):
        // bit-16 merges batches; bits 8/4/2/1 split components.
        float v[16];
        #pragma unroll
        for (int k = 0; k < 16; k++) {
            float s = (lane & 16) ? v0[k] : v1[k];
            float r = __shfl_xor_sync(0xffffffffu, s, 16);
            v[k] = ((lane & 16) ? v1[k] : v0[k]) + r;
        }
        #pragma unroll
        for (int k = 0; k < 8; k++) {
            float s = (lane & 8) ? v[k] : v[k + 8];
            float r = __shfl_xor_sync(0xffffffffu, s, 8);
            v[k] = ((lane & 8) ? v[k + 8] : v[k]) + r;
        }
        #pragma unroll
        for (int k = 0; k < 4; k++) {
            float s = (lane & 4) ? v[k] : v[k + 4];
            float r = __shfl_xor_sync(0xffffffffu, s, 4);
            v[k] = ((lane & 4) ? v[k + 4] : v[k]) + r;
        }
        #pragma unroll
        for (int k = 0; k < 2; k++) {
            float s = (lane & 2) ? v[k] : v[k + 2];
            float r = __shfl_xor_sync(0xffffffffu, s, 2);
            v[k] = ((lane & 2) ? v[k + 2] : v[k]) + r;
        }
        {
            float s = (lane & 1) ? v[0] : v[1];
            float r = __shfl_xor_sync(0xffffffffu, s, 1);
            v[0] = ((lane & 1) ? v[1] : v[0]) + r;
        }
        vred[w * 32 + lane] = v[0];

        if (it > 0) {   // sp: merge batches then butterfly
            float s = (lane & 16) ? sp0 : sp1;
            float r = __shfl_xor_sync(0xffffffffu, s, 16);
            float sp = ((lane & 16) ? sp1 : sp0) + r;
            #pragma unroll
            for (int d = 8; d; d >>= 1)
                sp += __shfl_xor_sync(0xffffffffu, sp, d);
            if ((lane & 15) == 0) spred[w * 2 + (lane >> 4)] = sp;
        }
        __syncthreads();

        // --- final 18-way reduce + squash (warp 0: lanes 0-15 bb0, 16-31 bb1) ---
        if (tid < 32) {
            const int fb = tid >> 4;
            float O = 0.f;
            #pragma unroll
            for (int j = 0; j < NWARPS; j++) O += vred[j * 32 + tid];
            float S;
            if (it == 0) {
                S = (float)ND;
            } else {
                S = 0.f;
                #pragma unroll
                for (int j = 0; j < NWARPS; j++) S += spred[j * 2 + fb];
            }
            float t = O / S;
            float sq = t * t;
            #pragma unroll
            for (int d = 8; d; d >>= 1)
                sq += __shfl_xor_sync(0xffffffffu, sq, d);
            float scale = sq / ((1.f + sq) * sqrtf(sq + 1e-8f));
            float val = t * scale;
            outv[tid] = val;
            if (it == 2)
                out[((size_t)(c * BD + b0 + fb)) * OUTD + (tid & 15)] = val;
        }
        __syncthreads();
    }
}

extern "C" void kernel_launch(void* const* d_in, const int* in_sizes, int n_in,
                              void* d_out, int out_size)
{
    const float* x = (const float*)d_in[0];
    const float* W = (const float*)d_in[1];
    // defensive: identify by size (x: 1,179,648 ; W: 1,474,560)
    if (n_in >= 2 && in_sizes[0] == CCAP * ND * 8 * OUTD) {
        x = (const float*)d_in[1];
        W = (const float*)d_in[0];
    }
    float* out = (float*)d_out;

    transpose_inputs_kernel<<<TP_WBLOCKS + TP_XBLOCKS, 256>>>(
        (const float4*)W, (const float4*)x);

    caps_routing_kernel<<<NBLOCKS, THREADS>>>(out);
}